// round 6
// baseline (speedup 1.0000x reference)
#include <cuda_runtime.h>

// ---------------------------------------------------------------------------
// UHGAnomalyLoss:
//   loss = mean_E quad(p_src, p_dst) + mean_N quad(p, origin)
//          + 0.1 * mean_{first 10 edges} quad(line_src, line_dst)
// p = (x, y, 1) from z[:, 0:2], origin = (0,0,1),
// inner(a,b) = -(a0 b0 + a1 b1) + a2 b2,
// quad(a,b) = (ab^2 - aa*bb) / (max(|aa*bb|, EPS)*sign(aa*bb)),
// line(p) = cross(p, origin) = (y, -x, 0).
// ---------------------------------------------------------------------------

#define N_NODES_C 200000
#define N_EDGES_C 12800000
#define DIM_C     128
#define EPSF      1e-9f

#define TPB       256
#define GRID_P    782     // ceil(200000 / 256): one node per thread
#define GRID_E    1184    // 148 SMs * 8 resident-block slots (2/SM at 256thr)
#define EPI       16      // edges per thread per iteration

// Scratch (device globals: no allocation allowed anywhere)
__device__ float2   g_xy[N_NODES_C];
__device__ double   g_prox_part[GRID_E];
__device__ double   g_comp_part[GRID_P];
__device__ unsigned g_ticket;

__device__ __forceinline__ float safe_den(float den) {
    return copysignf(fmaxf(fabsf(den), EPSF), den);
}

__device__ __forceinline__ double block_reduce(double v) {
    __shared__ double sh[TPB];
    sh[threadIdx.x] = v;
    __syncthreads();
    #pragma unroll
    for (int off = TPB / 2; off > 0; off >>= 1) {
        if (threadIdx.x < off) sh[threadIdx.x] += sh[threadIdx.x + off];
        __syncthreads();
    }
    double r = sh[0];
    __syncthreads();
    return r;
}

// ---------------------------------------------------------------------------
// Kernel 1: pack (x,y) into dense table + per-node compactness partials.
// compactness: aa = 1 - x^2 - y^2, bb = ab = 1 -> quad = (1 - aa)/safe(aa)
// Also resets the finalize ticket (stream-ordered before the edge kernel).
// ---------------------------------------------------------------------------
__global__ void __launch_bounds__(TPB) prep_kernel(const float* __restrict__ z) {
    const int i = blockIdx.x * TPB + threadIdx.x;
    if (i == 0) g_ticket = 0u;

    double q = 0.0;
    if (i < N_NODES_C) {
        const float2 v = __ldg((const float2*)(z + (size_t)i * DIM_C));
        g_xy[i] = v;
        const float aa = 1.0f - v.x * v.x - v.y * v.y;
        q = (double)__fdividef(1.0f - aa, safe_den(aa));
    }
    const double s = block_reduce(q);
    if (threadIdx.x == 0) g_comp_part[blockIdx.x] = s;
}

// ---------------------------------------------------------------------------
// Kernel 2: proximity over all edges. 16 edges/thread/iter, gathers
// front-batched for maximum memory-level parallelism.
// ---------------------------------------------------------------------------
__device__ __forceinline__ float quad_xy(float2 a, float2 b) {
    const float aa  = 1.0f - a.x * a.x - a.y * a.y;
    const float bb  = 1.0f - b.x * b.x - b.y * b.y;
    const float ab  = 1.0f - a.x * b.x - a.y * b.y;
    const float den = aa * bb;
    const float num = fmaf(ab, ab, -den);
    return __fdividef(num, safe_den(den));
}

__global__ void __launch_bounds__(TPB, 2) edge_kernel(const int* __restrict__ ei,
                                                      float* __restrict__ out) {
    const int4* __restrict__ src4 = (const int4*)ei;
    const int4* __restrict__ dst4 = (const int4*)(ei + N_EDGES_C);
    const int tid    = blockIdx.x * TPB + threadIdx.x;
    const int nIter  = N_EDGES_C / EPI;        // 800K iterations of 16 edges
    const int stride = GRID_E * TPB;

    double dsum = 0.0;
    for (int i = tid; i < nIter; i += stride) {
        // 16 edge indices per endpoint (coalesced 128B/warp bursts)
        int4 s[4], d[4];
        #pragma unroll
        for (int k = 0; k < 4; k++) {
            s[k] = __ldg(&src4[i * 4 + k]);
            d[k] = __ldg(&dst4[i * 4 + k]);
        }
        // Front-batch all 32 gathers -> deep LDG queue, hides L1tex latency.
        float2 a[EPI], b[EPI];
        #pragma unroll
        for (int k = 0; k < 4; k++) {
            a[k * 4 + 0] = __ldg(&g_xy[s[k].x]);
            a[k * 4 + 1] = __ldg(&g_xy[s[k].y]);
            a[k * 4 + 2] = __ldg(&g_xy[s[k].z]);
            a[k * 4 + 3] = __ldg(&g_xy[s[k].w]);
        }
        #pragma unroll
        for (int k = 0; k < 4; k++) {
            b[k * 4 + 0] = __ldg(&g_xy[d[k].x]);
            b[k * 4 + 1] = __ldg(&g_xy[d[k].y]);
            b[k * 4 + 2] = __ldg(&g_xy[d[k].z]);
            b[k * 4 + 3] = __ldg(&g_xy[d[k].w]);
        }
        float part = 0.0f;
        #pragma unroll
        for (int k = 0; k < EPI; k++) part += quad_xy(a[k], b[k]);
        dsum += (double)part;   // one double promote per 16 edges
    }

    const double bsum = block_reduce(dsum);
    if (threadIdx.x == 0) g_prox_part[blockIdx.x] = bsum;

    // ---- last-block finalize ----
    __shared__ bool s_last;
    __threadfence();
    if (threadIdx.x == 0)
        s_last = (atomicAdd(&g_ticket, 1u) == (unsigned)(GRID_E - 1));
    __syncthreads();
    if (!s_last) return;

    const int t = threadIdx.x;
    double p = 0.0;
    for (int i = t; i < GRID_E; i += TPB) p += g_prox_part[i];
    const double prox_sum = block_reduce(p);

    double c = 0.0;
    for (int i = t; i < GRID_P; i += TPB) c += g_comp_part[i];
    const double comp_sum = block_reduce(c);

    if (t == 0) {
        double ssum = 0.0;
        const int n_sp = 10;  // min(10, E)
        for (int k = 0; k < n_sp; k++) {
            const int sI = ei[k];
            const int dI = ei[N_EDGES_C + k];
            const float2 a = g_xy[sI];
            const float2 b = g_xy[dI];
            // lines: la = (a.y, -a.x, 0), lb = (b.y, -b.x, 0)
            const float aa  = -(a.y * a.y + a.x * a.x);
            const float bb  = -(b.y * b.y + b.x * b.x);
            const float ab  = -(a.y * b.y + a.x * b.x);
            const float den = aa * bb;
            const float num = fmaf(ab, ab, -den);
            ssum += (double)__fdividef(num, safe_den(den));
        }
        const double loss = prox_sum / (double)N_EDGES_C
                          + comp_sum / (double)N_NODES_C
                          + 0.1 * (ssum / (double)n_sp);
        out[0] = (float)loss;
    }
}

// ---------------------------------------------------------------------------
extern "C" void kernel_launch(void* const* d_in, const int* in_sizes, int n_in,
                              void* d_out, int out_size) {
    const float* z   = (const float*)d_in[0];
    const int*   ei  = (const int*)d_in[1];
    float*       out = (float*)d_out;

    prep_kernel<<<GRID_P, TPB>>>(z);
    edge_kernel<<<GRID_E, TPB>>>(ei, out);
}